// round 12
// baseline (speedup 1.0000x reference)
#include <cuda_runtime.h>
#include <cuda_fp16.h>
#include <cstdint>

// x[32768,2048] fp32, bank[20,2048] fp32 -> out[32768,2048] fp32
constexpr int FEA    = 2048;
constexpr int NBANK  = 20;
constexpr int TILE_M = 32;             // 1024 tiles
constexpr int CHUNK  = 256;            // x cols per chunk
constexpr int NCH    = FEA / CHUNK;    // 8
constexpr float LAMBDA = 0.0025f;

// SMEM map (169984 B -> 1 CTA/SM)
constexpr int SM_BANK  = 0;                        // [32 j pad][2048 k] fp16 swz
constexpr int BANKB    = 32 * FEA * 2;             // 131072
constexpr int SM_X     = BANKB;                    // x fp16 ring: 2 x 16KB
constexpr int XSLOTB   = TILE_M * CHUNK * 2;       // 16384
constexpr int SM_LOGIT = SM_X + 2 * XSLOTB;        // 163840: [32][32] f32
constexpr int SM_ATT   = SM_LOGIT + 32 * 32 * 4;   // 167936: [32][32] fp16
constexpr int SM_TOTAL = SM_ATT + 32 * 32 * 2;     // 169984

__device__ __forceinline__ uint32_t s2u(const void* p) {
    uint32_t a;
    asm("{ .reg .u64 t; cvta.to.shared.u64 t, %1; cvt.u32.u64 %0, t; }"
        : "=r"(a) : "l"(p));
    return a;
}
__device__ __forceinline__ void ldsm4(uint32_t a, uint32_t& r0, uint32_t& r1,
                                      uint32_t& r2, uint32_t& r3) {
    asm volatile("ldmatrix.sync.aligned.m8n8.x4.shared.b16 {%0,%1,%2,%3}, [%4];"
                 : "=r"(r0), "=r"(r1), "=r"(r2), "=r"(r3) : "r"(a));
}
__device__ __forceinline__ void ldsm2(uint32_t a, uint32_t& r0, uint32_t& r1) {
    asm volatile("ldmatrix.sync.aligned.m8n8.x2.shared.b16 {%0,%1}, [%2];"
                 : "=r"(r0), "=r"(r1) : "r"(a));
}
__device__ __forceinline__ void ldsm4t(uint32_t a, uint32_t& r0, uint32_t& r1,
                                       uint32_t& r2, uint32_t& r3) {
    asm volatile("ldmatrix.sync.aligned.m8n8.x4.trans.shared.b16 {%0,%1,%2,%3}, [%4];"
                 : "=r"(r0), "=r"(r1), "=r"(r2), "=r"(r3) : "r"(a));
}
__device__ __forceinline__ void mma16816(float& d0, float& d1, float& d2, float& d3,
                                         uint32_t a0, uint32_t a1, uint32_t a2, uint32_t a3,
                                         uint32_t b0, uint32_t b1) {
    asm volatile(
        "mma.sync.aligned.m16n8k16.row.col.f32.f16.f16.f32 "
        "{%0,%1,%2,%3}, {%4,%5,%6,%7}, {%8,%9}, {%0,%1,%2,%3};"
        : "+f"(d0), "+f"(d1), "+f"(d2), "+f"(d3)
        : "r"(a0), "r"(a1), "r"(a2), "r"(a3), "r"(b0), "r"(b1));
}
__device__ __forceinline__ float tanh_fast(float v) {
    float r;
    asm("tanh.approx.f32 %0, %1;" : "=f"(r) : "f"(v));
    return r;
}
__device__ __forceinline__ uint32_t h2bits(__half2 h) {
    return *reinterpret_cast<uint32_t*>(&h);
}

extern __shared__ char smc[];

__global__ void __launch_bounds__(256, 1)
memunit_pipe2(const float* __restrict__ x,
              const float* __restrict__ bank,
              float* __restrict__ out,
              int n_tiles)
{
    const uint32_t sbase = s2u(smc);
    const int tid  = threadIdx.x;
    const int warp = tid >> 5;
    const int lane = tid & 31;
    const int G    = gridDim.x;

    // ---- bank -> fp16 [32 j pad][2048], swizzle byte = j*4096 + (2k ^ ((j&7)<<4))
    for (int i = tid; i < BANKB / 16; i += 256)
        reinterpret_cast<uint4*>(smc + SM_BANK)[i] = make_uint4(0, 0, 0, 0);
    __syncthreads();
    for (int idx = tid; idx < NBANK * FEA; idx += 256) {
        const int j = idx >> 11, k = idx & (FEA - 1);
        *reinterpret_cast<__half*>(smc + SM_BANK + j * 4096 + ((2 * k) ^ ((j & 7) << 4)))
            = __float2half(bank[idx]);
    }
    __syncthreads();

    const int mh = warp >> 2;              // GEMM1 m-half
    const int nt = warp & 3;               // GEMM1 n-tile

    // GEMM1 A frags (row-major x4)
    const int arow = mh * 16 + (lane & 7) + ((lane & 8) ? 8 : 0);
    const int akb  = (lane & 16) ? 16 : 0;
    const int asw  = (arow & 7) << 4;
    // GEMM1 B (non-trans x2): rows j = nt*8 + (lane&7)
    const int brow = nt * 8 + (lane & 7);
    const int bkb  = (lane & 8) ? 16 : 0;
    const int bsw  = (brow & 7) << 4;
    const uint32_t bb = sbase + SM_BANK + brow * 4096;
    // GEMM2 B (trans x4): j = lane (rows 20-31 zero pad)
    const uint32_t btl = sbase + SM_BANK + lane * 4096;
    const int swj = (lane & 7) << 4;
    // GEMM1 logit rows
    const int lr  = mh * 16 + (lane >> 2);
    const int lc2 = (lane & 3) * 2;
    // GEMM2: rows lane>>2 + {0,8,16,24}; att frag row component
    const int frow = (lane & 7) + ((lane & 8) ? 8 : 0);
    const int fkb  = (lane & 16) ? 16 : 0;

    float4 pf[8];   // x prefetch: 32 f32 per thread (one 32x256 chunk)

    auto ldx = [&](int tile, int c) {
        const float4* p = reinterpret_cast<const float4*>(x)
                        + (long)tile * TILE_M * (FEA / 4) + c * (CHUNK / 4);
        #pragma unroll
        for (int i = 0; i < 8; i++) {
            const int f = i * 256 + tid;              // float4 idx in chunk
            pf[i] = __ldcs(&p[(f >> 6) * (FEA / 4) + (f & 63)]);
        }
    };
    auto stx = [&](int slot) {
        char* s = smc + SM_X + slot * XSLOTB;
        #pragma unroll
        for (int i = 0; i < 8; i++) {
            const int f = i * 256 + tid;
            const int row = f >> 6, kb = (f & 63) * 8;
            uint2 pkt;
            pkt.x = h2bits(__floats2half2_rn(pf[i].x, pf[i].y));
            pkt.y = h2bits(__floats2half2_rn(pf[i].z, pf[i].w));
            *reinterpret_cast<uint2*>(s + row * 512 + (kb ^ ((row & 7) << 4))) = pkt;
        }
    };

    const int my_tiles = (n_tiles - (int)blockIdx.x + G - 1) / G;
    if (my_tiles <= 0) return;

    // att frags for BOTH m-blocks of the write tile (persist across iteration)
    uint32_t aA0[4], aA1[4], aB0[4], aB1[4];
    ldx((int)blockIdx.x, 0);

    // Iteration it: GEMM1 for tile it (if any) + GEMM2 for tile it-1 (if any).
    for (int it = 0; it <= my_tiles; it++) {
        const bool hasG1 = it < my_tiles;
        const bool hasG2 = it > 0;
        const int  tile1 = (int)blockIdx.x + it * G;
        const long row0w = (long)((int)blockIdx.x + (it - 1) * G) * TILE_M;

        float d0 = 0.f, d1 = 0.f, d2 = 0.f, d3 = 0.f;

        #pragma unroll 1
        for (int c = 0; c < NCH; c++) {
            if (hasG1) {
                stx(c & 1);
                if (c + 1 < NCH)            ldx(tile1, c + 1);
                else if (it + 1 < my_tiles) ldx(tile1 + G, 0);
            }
            __syncthreads();    // xh[c&1] ready (double-buffer: one bar suffices)

            if (hasG1) {
                const uint32_t xs = sbase + SM_X + (c & 1) * XSLOTB + arow * 512;
                #pragma unroll
                for (int ks = 0; ks < 16; ks++) {
                    uint32_t a0, a1, a2, a3, b0, b1;
                    ldsm4(xs + ((ks * 32 + akb) ^ asw), a0, a1, a2, a3);
                    ldsm2(bb + ((c * 512 + ks * 32 + bkb) ^ bsw), b0, b1);
                    mma16816(d0, d1, d2, d3, a0, a1, a2, a3, b0, b1);
                }
            }

            // GEMM2 + tanh: warp owns its 256-col slice for ALL 32 rows,
            // executed at chunk c == warp (staggers writes across chunks).
            if (hasG2 && c == warp) {
                float* o0 = out + (row0w + (lane >> 2)) * FEA + lc2;
                const int colbase = warp * 256;
                #pragma unroll 4
                for (int t2 = 0; t2 < 32; t2++) {
                    const int nb = colbase + t2 * 8;
                    uint32_t b00, b01, b10, b11;
                    ldsm4t(btl + ((nb * 2) ^ swj), b00, b01, b10, b11);
                    float e0 = 0.f, e1 = 0.f, e2 = 0.f, e3 = 0.f;
                    float f0 = 0.f, f1 = 0.f, f2 = 0.f, f3 = 0.f;
                    mma16816(e0, e1, e2, e3, aA0[0], aA0[1], aA0[2], aA0[3], b00, b01);
                    mma16816(e0, e1, e2, e3, aA1[0], aA1[1], aA1[2], aA1[3], b10, b11);
                    mma16816(f0, f1, f2, f3, aB0[0], aB0[1], aB0[2], aB0[3], b00, b01);
                    mma16816(f0, f1, f2, f3, aB1[0], aB1[1], aB1[2], aB1[3], b10, b11);
                    __stcs(reinterpret_cast<float2*>(o0 + nb),
                           make_float2(tanh_fast(e0), tanh_fast(e1)));
                    __stcs(reinterpret_cast<float2*>(o0 + 8 * FEA + nb),
                           make_float2(tanh_fast(e2), tanh_fast(e3)));
                    __stcs(reinterpret_cast<float2*>(o0 + 16 * FEA + nb),
                           make_float2(tanh_fast(f0), tanh_fast(f1)));
                    __stcs(reinterpret_cast<float2*>(o0 + 24 * FEA + nb),
                           make_float2(tanh_fast(f2), tanh_fast(f3)));
                }
            }
        }

        if (hasG1) {
            // ---- logits -> SMEM ------------------------------------------
            float* lg = reinterpret_cast<float*>(smc + SM_LOGIT);
            *reinterpret_cast<float2*>(&lg[lr * 32 + nt * 8 + lc2])       = make_float2(d0, d1);
            *reinterpret_cast<float2*>(&lg[(lr + 8) * 32 + nt * 8 + lc2]) = make_float2(d2, d3);
            __syncthreads();

            // ---- softmax -> softshrink -> softmax (1 thr/row) ------------
            if (tid < 32) {
                float att[NBANK];
                #pragma unroll
                for (int j = 0; j < NBANK; j++) att[j] = lg[tid * 32 + j];

                float m = att[0];
                #pragma unroll
                for (int j = 1; j < NBANK; j++) m = fmaxf(m, att[j]);
                float s = 0.f;
                #pragma unroll
                for (int j = 0; j < NBANK; j++) { float e = __expf(att[j] - m); att[j] = e; s += e; }
                const float inv = 1.0f / s;

                float m2 = 0.f;   // att >= 0 => softshrink = max(att - lambda, 0)
                #pragma unroll
                for (int j = 0; j < NBANK; j++) {
                    float a = fmaxf(att[j] * inv - LAMBDA, 0.f);
                    att[j] = a;
                    m2 = fmaxf(m2, a);
                }
                float s2 = 0.f;
                #pragma unroll
                for (int j = 0; j < NBANK; j++) { float e = __expf(att[j] - m2); att[j] = e; s2 += e; }
                const float inv2 = 1.0f / s2;

                __half2* av = reinterpret_cast<__half2*>(smc + SM_ATT + tid * 64);
                #pragma unroll
                for (int jp = 0; jp < 10; jp++)
                    av[jp] = __floats2half2_rn(att[2 * jp] * inv2, att[2 * jp + 1] * inv2);
                #pragma unroll
                for (int jp = 10; jp < 16; jp++)
                    av[jp] = __floats2half2_rn(0.f, 0.f);
            }
            __syncthreads();

            // ---- preload att frags (both m-blocks) for next GEMM2 --------
            const uint32_t ab0 = sbase + SM_ATT + frow * 64 + fkb;          // rows 0-15
            const uint32_t ab1 = sbase + SM_ATT + (16 + frow) * 64 + fkb;   // rows 16-31
            ldsm4(ab0,      aA0[0], aA0[1], aA0[2], aA0[3]);   // k = j 0..15
            ldsm4(ab0 + 32, aA1[0], aA1[1], aA1[2], aA1[3]);   // k = j 16..31
            ldsm4(ab1,      aB0[0], aB0[1], aB0[2], aB0[3]);
            ldsm4(ab1 + 32, aB1[0], aB1[1], aB1[2], aB1[3]);
        }
    }
}

extern "C" void kernel_launch(void* const* d_in, const int* in_sizes, int n_in,
                              void* d_out, int out_size)
{
    const float* x    = reinterpret_cast<const float*>(d_in[0]);
    const float* bank = reinterpret_cast<const float*>(d_in[1]);
    float* out        = reinterpret_cast<float*>(d_out);

    const int rows    = in_sizes[0] / FEA;   // 32768
    const int n_tiles = rows / TILE_M;       // 1024

    cudaFuncSetAttribute(memunit_pipe2,
                         cudaFuncAttributeMaxDynamicSharedMemorySize, SM_TOTAL);

    int dev = 0, sms = 148;
    cudaGetDevice(&dev);
    cudaDeviceGetAttribute(&sms, cudaDevAttrMultiProcessorCount, dev);

    const int grid = (sms < n_tiles) ? sms : n_tiles;
    memunit_pipe2<<<grid, 256, SM_TOTAL>>>(x, bank, out, n_tiles);
}

// round 13
// speedup vs baseline: 1.3506x; 1.3506x over previous
#include <cuda_runtime.h>
#include <cuda_fp16.h>
#include <cstdint>

// x[32768,2048] fp32, bank[20,2048] fp32 -> out[32768,2048] fp32
constexpr int FEA    = 2048;
constexpr int NBANK  = 20;
constexpr int TILE_M = 32;             // 1024 tiles
constexpr int CHUNK  = 256;            // x cols per chunk
constexpr int NCH    = FEA / CHUNK;    // 8
constexpr int NTH    = 512;            // 16 warps
constexpr float LAMBDA = 0.0025f;

// SMEM map (174080 B -> 1 CTA/SM)
constexpr int SM_BANK  = 0;                        // [32 j pad][2048 k] fp16 swz
constexpr int BANKB    = 32 * FEA * 2;             // 131072
constexpr int SM_X     = BANKB;                    // x fp16 ring: 2 x 16KB
constexpr int XSLOTB   = TILE_M * CHUNK * 2;       // 16384
constexpr int SM_LOGIT = SM_X + 2 * XSLOTB;        // 163840: 2 x [32][32] f32
constexpr int LOGB     = 32 * 32 * 4;              // 4096
constexpr int SM_ATT   = SM_LOGIT + 2 * LOGB;      // 172032: [32][32] fp16
constexpr int SM_TOTAL = SM_ATT + 32 * 32 * 2;     // 174080

__device__ __forceinline__ uint32_t s2u(const void* p) {
    uint32_t a;
    asm("{ .reg .u64 t; cvta.to.shared.u64 t, %1; cvt.u32.u64 %0, t; }"
        : "=r"(a) : "l"(p));
    return a;
}
__device__ __forceinline__ void ldsm4(uint32_t a, uint32_t& r0, uint32_t& r1,
                                      uint32_t& r2, uint32_t& r3) {
    asm volatile("ldmatrix.sync.aligned.m8n8.x4.shared.b16 {%0,%1,%2,%3}, [%4];"
                 : "=r"(r0), "=r"(r1), "=r"(r2), "=r"(r3) : "r"(a));
}
__device__ __forceinline__ void ldsm2(uint32_t a, uint32_t& r0, uint32_t& r1) {
    asm volatile("ldmatrix.sync.aligned.m8n8.x2.shared.b16 {%0,%1}, [%2];"
                 : "=r"(r0), "=r"(r1) : "r"(a));
}
__device__ __forceinline__ void ldsm4t(uint32_t a, uint32_t& r0, uint32_t& r1,
                                       uint32_t& r2, uint32_t& r3) {
    asm volatile("ldmatrix.sync.aligned.m8n8.x4.trans.shared.b16 {%0,%1,%2,%3}, [%4];"
                 : "=r"(r0), "=r"(r1), "=r"(r2), "=r"(r3) : "r"(a));
}
__device__ __forceinline__ void mma16816(float& d0, float& d1, float& d2, float& d3,
                                         uint32_t a0, uint32_t a1, uint32_t a2, uint32_t a3,
                                         uint32_t b0, uint32_t b1) {
    asm volatile(
        "mma.sync.aligned.m16n8k16.row.col.f32.f16.f16.f32 "
        "{%0,%1,%2,%3}, {%4,%5,%6,%7}, {%8,%9}, {%0,%1,%2,%3};"
        : "+f"(d0), "+f"(d1), "+f"(d2), "+f"(d3)
        : "r"(a0), "r"(a1), "r"(a2), "r"(a3), "r"(b0), "r"(b1));
}
__device__ __forceinline__ float tanh_fast(float v) {
    float r;
    asm("tanh.approx.f32 %0, %1;" : "=f"(r) : "f"(v));
    return r;
}
__device__ __forceinline__ uint32_t h2bits(__half2 h) {
    return *reinterpret_cast<uint32_t*>(&h);
}

extern __shared__ char smc[];

__global__ void __launch_bounds__(NTH, 1)
memunit_w16(const float* __restrict__ x,
            const float* __restrict__ bank,
            float* __restrict__ out,
            int n_tiles)
{
    const uint32_t sbase = s2u(smc);
    const int tid  = threadIdx.x;
    const int warp = tid >> 5;
    const int lane = tid & 31;
    const int G    = gridDim.x;

    // ---- bank -> fp16 [32 j pad][2048], swizzle byte = j*4096 + (2k ^ ((j&7)<<4))
    for (int i = tid; i < BANKB / 16; i += NTH)
        reinterpret_cast<uint4*>(smc + SM_BANK)[i] = make_uint4(0, 0, 0, 0);
    __syncthreads();
    for (int idx = tid; idx < NBANK * FEA; idx += NTH) {
        const int j = idx >> 11, k = idx & (FEA - 1);
        *reinterpret_cast<__half*>(smc + SM_BANK + j * 4096 + ((2 * k) ^ ((j & 7) << 4)))
            = __float2half(bank[idx]);
    }
    __syncthreads();

    // GEMM1 decomposition: 16 warps = mh(2) x nt(4) x kh(2)
    const int mh = warp >> 3;              // m-half: rows mh*16..+15
    const int nt = (warp >> 1) & 3;        // n-tile: logits cols nt*8..+7
    const int kh = warp & 1;               // k-half: ks 8*kh .. 8*kh+7

    // A frags (row-major x4)
    const int arow = mh * 16 + (lane & 7) + ((lane & 8) ? 8 : 0);
    const int akb  = (lane & 16) ? 16 : 0;
    const int asw  = (arow & 7) << 4;
    // GEMM1 B (non-trans x2): rows j = nt*8 + (lane&7)
    const int brow = nt * 8 + (lane & 7);
    const int bkb  = (lane & 8) ? 16 : 0;
    const int bsw  = (brow & 7) << 4;
    const uint32_t bb = sbase + SM_BANK + brow * 4096;
    // GEMM2 decomposition: 16 warps = mh2(2) x nt2(8)
    const int mh2 = warp >> 3;
    const int nt2 = warp & 7;
    // GEMM2 B (trans x4): j = lane (rows 20-31 zero pad)
    const uint32_t btl = sbase + SM_BANK + lane * 4096;
    const int swj = (lane & 7) << 4;
    // logit / out row mapping
    const int lr  = mh * 16 + (lane >> 2);
    const int lc2 = (lane & 3) * 2;
    // att frag row component (for mh2 block)
    const int frow = (lane & 7) + ((lane & 8) ? 8 : 0);
    const int fkb  = (lane & 16) ? 16 : 0;

    float4 pf[4];   // x prefetch: 16 f32 per thread (one 32x256 chunk / 512 thr)

    auto ldx = [&](int tile, int c) {
        const float4* p = reinterpret_cast<const float4*>(x)
                        + (long)tile * TILE_M * (FEA / 4) + c * (CHUNK / 4);
        #pragma unroll
        for (int i = 0; i < 4; i++) {
            const int f = i * NTH + tid;              // float4 idx in chunk
            pf[i] = p[(f >> 6) * (FEA / 4) + (f & 63)];
        }
    };
    auto stx = [&](int slot) {
        char* s = smc + SM_X + slot * XSLOTB;
        #pragma unroll
        for (int i = 0; i < 4; i++) {
            const int f = i * NTH + tid;
            const int row = f >> 6, kb = (f & 63) * 8;
            uint2 pkt;
            pkt.x = h2bits(__floats2half2_rn(pf[i].x, pf[i].y));
            pkt.y = h2bits(__floats2half2_rn(pf[i].z, pf[i].w));
            *reinterpret_cast<uint2*>(s + row * 512 + (kb ^ ((row & 7) << 4))) = pkt;
        }
    };

    const int my_tiles = (n_tiles - (int)blockIdx.x + G - 1) / G;
    if (my_tiles <= 0) return;

    uint32_t aA0[4], aA1[4];   // att frags (mh2 block) for the write tile
    ldx((int)blockIdx.x, 0);

    // Iteration it: GEMM1 for tile it (if any) + GEMM2 for tile it-1 (if any).
    for (int it = 0; it <= my_tiles; it++) {
        const bool hasG1 = it < my_tiles;
        const bool hasG2 = it > 0;
        const int  tile1 = (int)blockIdx.x + it * G;
        const long row0w = (long)((int)blockIdx.x + (it - 1) * G) * TILE_M;

        float d0 = 0.f, d1 = 0.f, d2 = 0.f, d3 = 0.f;
        float* orow0 = out + (row0w + mh2 * 16 + (lane >> 2)) * FEA + lc2;

        #pragma unroll 1
        for (int c = 0; c < NCH; c++) {
            if (hasG1) {
                stx(c & 1);
                if (c + 1 < NCH)            ldx(tile1, c + 1);
                else if (it + 1 < my_tiles) ldx(tile1 + G, 0);
            }
            __syncthreads();    // xh[c&1] ready (double-buffer: one bar suffices)

            if (hasG1) {
                // this warp's k-half of the chunk: ks = kh*8 .. kh*8+7
                const uint32_t xs = sbase + SM_X + (c & 1) * XSLOTB + arow * 512;
                #pragma unroll
                for (int s = 0; s < 8; s++) {
                    const int ks = kh * 8 + s;
                    uint32_t a0, a1, a2, a3, b0, b1;
                    ldsm4(xs + ((ks * 32 + akb) ^ asw), a0, a1, a2, a3);
                    ldsm2(bb + ((c * 512 + ks * 32 + bkb) ^ bsw), b0, b1);
                    mma16816(d0, d1, d2, d3, a0, a1, a2, a3, b0, b1);
                }
            }

            if (hasG2) {
                // GEMM2 + tanh: warp's 4 n8-blocks within this 256-col chunk
                #pragma unroll
                for (int i = 0; i < 4; i++) {
                    const int nb = c * 256 + nt2 * 32 + i * 8;
                    uint32_t b00, b01, b10, b11;
                    ldsm4t(btl + ((nb * 2) ^ swj), b00, b01, b10, b11);
                    float e0 = 0.f, e1 = 0.f, e2 = 0.f, e3 = 0.f;
                    mma16816(e0, e1, e2, e3, aA0[0], aA0[1], aA0[2], aA0[3], b00, b01);
                    mma16816(e0, e1, e2, e3, aA1[0], aA1[1], aA1[2], aA1[3], b10, b11);
                    *reinterpret_cast<float2*>(orow0 + nb) =
                        make_float2(tanh_fast(e0), tanh_fast(e1));
                    *reinterpret_cast<float2*>(orow0 + 8 * FEA + nb) =
                        make_float2(tanh_fast(e2), tanh_fast(e3));
                }
            }
        }

        if (hasG1) {
            // ---- partial logits -> SMEM (per k-half buffer) --------------
            float* lg = reinterpret_cast<float*>(smc + SM_LOGIT + kh * LOGB);
            *reinterpret_cast<float2*>(&lg[lr * 32 + nt * 8 + lc2])       = make_float2(d0, d1);
            *reinterpret_cast<float2*>(&lg[(lr + 8) * 32 + nt * 8 + lc2]) = make_float2(d2, d3);
            __syncthreads();

            // ---- softmax -> softshrink -> softmax (1 thr/row) ------------
            if (tid < 32) {
                const float* lg0 = reinterpret_cast<const float*>(smc + SM_LOGIT);
                const float* lg1 = reinterpret_cast<const float*>(smc + SM_LOGIT + LOGB);
                float att[NBANK];
                #pragma unroll
                for (int j = 0; j < NBANK; j++)
                    att[j] = lg0[tid * 32 + j] + lg1[tid * 32 + j];

                float m = att[0];
                #pragma unroll
                for (int j = 1; j < NBANK; j++) m = fmaxf(m, att[j]);
                float s = 0.f;
                #pragma unroll
                for (int j = 0; j < NBANK; j++) { float e = __expf(att[j] - m); att[j] = e; s += e; }
                const float inv = 1.0f / s;

                float m2 = 0.f;   // att >= 0 => softshrink = max(att - lambda, 0)
                #pragma unroll
                for (int j = 0; j < NBANK; j++) {
                    float a = fmaxf(att[j] * inv - LAMBDA, 0.f);
                    att[j] = a;
                    m2 = fmaxf(m2, a);
                }
                float s2 = 0.f;
                #pragma unroll
                for (int j = 0; j < NBANK; j++) { float e = __expf(att[j] - m2); att[j] = e; s2 += e; }
                const float inv2 = 1.0f / s2;

                __half2* av = reinterpret_cast<__half2*>(smc + SM_ATT + tid * 64);
                #pragma unroll
                for (int jp = 0; jp < 10; jp++)
                    av[jp] = __floats2half2_rn(att[2 * jp] * inv2, att[2 * jp + 1] * inv2);
                #pragma unroll
                for (int jp = 10; jp < 16; jp++)
                    av[jp] = __floats2half2_rn(0.f, 0.f);
            }
            __syncthreads();

            // ---- preload att frags (this warp's mh2 block) ---------------
            const uint32_t ab = sbase + SM_ATT + (mh2 * 16 + frow) * 64 + fkb;
            ldsm4(ab,      aA0[0], aA0[1], aA0[2], aA0[3]);   // k = j 0..15
            ldsm4(ab + 32, aA1[0], aA1[1], aA1[2], aA1[3]);   // k = j 16..31
        }
    }
}

extern "C" void kernel_launch(void* const* d_in, const int* in_sizes, int n_in,
                              void* d_out, int out_size)
{
    const float* x    = reinterpret_cast<const float*>(d_in[0]);
    const float* bank = reinterpret_cast<const float*>(d_in[1]);
    float* out        = reinterpret_cast<float*>(d_out);

    const int rows    = in_sizes[0] / FEA;   // 32768
    const int n_tiles = rows / TILE_M;       // 1024

    cudaFuncSetAttribute(memunit_w16,
                         cudaFuncAttributeMaxDynamicSharedMemorySize, SM_TOTAL);

    int dev = 0, sms = 148;
    cudaGetDevice(&dev);
    cudaDeviceGetAttribute(&sms, cudaDevAttrMultiProcessorCount, dev);

    const int grid = (sms < n_tiles) ? sms : n_tiles;
    memunit_w16<<<grid, NTH, SM_TOTAL>>>(x, bank, out, n_tiles);
}